// round 7
// baseline (speedup 1.0000x reference)
#include <cuda_runtime.h>
#include <cuda_fp16.h>
#include <math.h>
#include <cstdint>

// ---------------- problem constants ----------------
#define B     1024
#define CIN   3
#define HW    32
#define GC    16
#define E     4
#define C1    64
#define C2    128
#define NC    100
#define FCIN  8192      // 128*8*8

#define NPIX  324       // 18*18 haloed conv1 output grid
#define ROWP  72        // padded row length (halves); 144B stride

#define OUT_PROBS_OFF (B*NC)
#define OUT_AUX_OFF   (B*NC + B*E)

typedef unsigned long long ull;

// ---- f32x2 helpers ----
__device__ __forceinline__ ull ffma2(ull a, ull b, ull c) {
    ull d;
    asm("fma.rn.f32x2 %0, %1, %2, %3;" : "=l"(d) : "l"(a), "l"(b), "l"(c));
    return d;
}
__device__ __forceinline__ void upk(ull v, float& lo, float& hi) {
    asm("mov.b64 {%0, %1}, %2;" : "=f"(lo), "=f"(hi) : "l"(v));
}

__device__ __forceinline__ uint32_t smem_u32(const void* p) {
    uint32_t a;
    asm("{ .reg .u64 t; cvta.to.shared.u64 t, %1; cvt.u32.u64 %0, t; }"
        : "=r"(a) : "l"(p));
    return a;
}
__device__ __forceinline__ void ldsm_x4(uint32_t& r0, uint32_t& r1,
                                        uint32_t& r2, uint32_t& r3, uint32_t a) {
    asm volatile("ldmatrix.sync.aligned.m8n8.x4.shared.b16 {%0,%1,%2,%3}, [%4];"
                 : "=r"(r0), "=r"(r1), "=r"(r2), "=r"(r3) : "r"(a));
}
__device__ __forceinline__ void ldsm_x2(uint32_t& r0, uint32_t& r1, uint32_t a) {
    asm volatile("ldmatrix.sync.aligned.m8n8.x2.shared.b16 {%0,%1}, [%2];"
                 : "=r"(r0), "=r"(r1) : "r"(a));
}
__device__ __forceinline__ void mma16816(float* d, const uint32_t* a,
                                         uint32_t b0, uint32_t b1) {
    asm volatile(
        "mma.sync.aligned.m16n8k16.row.col.f32.f16.f16.f32 "
        "{%0,%1,%2,%3}, {%4,%5,%6,%7}, {%8,%9}, {%0,%1,%2,%3};"
        : "+f"(d[0]), "+f"(d[1]), "+f"(d[2]), "+f"(d[3])
        : "r"(a[0]), "r"(a[1]), "r"(a[2]), "r"(a[3]), "r"(b0), "r"(b1));
}

// ---------------- device scratch (zero-initialized; halo/pad cells stay 0) ----
__device__ __half g_b1h[(size_t)B * NPIX * ROWP];   // conv1 out hi, [b][pix][ci]
__device__ __half g_b1l[(size_t)B * NPIX * ROWP];   // conv1 out lo
__device__ float  g_buf2[(size_t)B * C2 * 8 * 8];   // conv2+pool out
__device__ float  g_gpool[B * GC];
__device__ int    g_bidx[B];
__device__ float  g_bw[B];
__device__ int    g_list[E * B];
__device__ int    g_count[E];
__device__ __half g_w2h[(size_t)E * 9 * C2 * C1];   // [e][tap][co][ci]
__device__ __half g_w2l[(size_t)E * 9 * C2 * C1];

// ---------------- split + transpose conv2 weights; also zero counters ------
__global__ void prep_w2_kernel(const float* __restrict__ c2w) {
    int i = blockIdx.x * blockDim.x + threadIdx.x;
    if (blockIdx.x == 0 && threadIdx.x < E) g_count[threadIdx.x] = 0;
    if (i >= E * 9 * C2 * C1) return;
    int ci   = i & 63;
    int co   = (i >> 6) & 127;
    int rest = i >> 13;            // e*9 + tap
    int tap  = rest % 9;
    int e    = rest / 9;
    float v = c2w[(((size_t)(e * C2 + co)) * C1 + ci) * 9 + tap];
    __half h = __float2half_rn(v);
    g_w2h[i] = h;
    g_w2l[i] = __float2half_rn(v - __half2float(h));
}

// ---------------- gating conv (3->16) + relu + GAP ----------------
__global__ void __launch_bounds__(256) gate_conv_kernel(
    const float* __restrict__ x, const float* __restrict__ gcw,
    const float* __restrict__ gcb)
{
    __shared__ float xs[CIN * 34 * 34];
    __shared__ float wg[GC * 27];
    __shared__ float gb[GC];
    __shared__ float red[256];

    int b   = blockIdx.x;
    int tid = threadIdx.x;

    for (int i = tid; i < CIN * 34 * 34; i += 256) xs[i] = 0.f;
    __syncthreads();
    const float* xb = x + (size_t)b * CIN * HW * HW;
    for (int i = tid; i < CIN * HW * HW; i += 256) {
        int ci = i >> 10, y = (i >> 5) & 31, xx = i & 31;
        xs[(ci * 34 + y + 1) * 34 + xx + 1] = xb[i];
    }
    for (int i = tid; i < GC * 27; i += 256) wg[i] = gcw[i];
    if (tid < GC) gb[tid] = gcb[tid];
    __syncthreads();

    int co = tid >> 4;
    int ln = tid & 15;
    float w[27];
#pragma unroll
    for (int k = 0; k < 27; k++) w[k] = wg[co * 27 + k];
    float bias = gb[co];

    float s = 0.f;
    for (int p = ln; p < HW * HW; p += 16) {
        int y = p >> 5, xx = p & 31;
        float v = bias;
#pragma unroll
        for (int ci = 0; ci < CIN; ci++)
#pragma unroll
            for (int dy = 0; dy < 3; dy++)
#pragma unroll
                for (int dx = 0; dx < 3; dx++)
                    v = fmaf(xs[(ci * 34 + y + dy) * 34 + xx + dx],
                             w[ci * 9 + dy * 3 + dx], v);
        s += fmaxf(v, 0.f);
    }
    red[tid] = s;
    __syncthreads();
    if (ln == 0) {
        float t = 0.f;
#pragma unroll
        for (int j = 0; j < 16; j++) t += red[co * 16 + j];
        g_gpool[b * GC + co] = t * (1.f / (HW * HW));
    }
}

// ---------------- router ----------------
__global__ void router_kernel(const float* __restrict__ gfw,
                              const float* __restrict__ gfb,
                              float* __restrict__ out_probs)
{
    int b = blockIdx.x * blockDim.x + threadIdx.x;
    if (b >= B) return;
    float gp[GC];
#pragma unroll
    for (int k = 0; k < GC; k++) gp[k] = g_gpool[b * GC + k];

    float lg[E];
#pragma unroll
    for (int e = 0; e < E; e++) {
        float s = gfb[e];
#pragma unroll
        for (int k = 0; k < GC; k++) s = fmaf(gp[k], gfw[e * GC + k], s);
        lg[e] = s;
    }
    float mx = lg[0];
#pragma unroll
    for (int e = 1; e < E; e++) mx = fmaxf(mx, lg[e]);
    float ex[E], se = 0.f;
#pragma unroll
    for (int e = 0; e < E; e++) { ex[e] = expf(lg[e] - mx); se += ex[e]; }
    float inv = 1.f / se;

    float bw = -1.f; int bi = 0;
#pragma unroll
    for (int e = 0; e < E; e++) {
        float p = ex[e] * inv;
        out_probs[b * E + e] = p;
        if (p > bw) { bw = p; bi = e; }
    }
    g_bidx[b] = bi;
    g_bw[b]   = bw;
    int pos = atomicAdd(&g_count[bi], 1);
    g_list[bi * B + pos] = b;
}

// ---------------- aux loss ----------------
__global__ void aux_kernel(const float* __restrict__ probs, float* __restrict__ out)
{
    __shared__ float sm[256 * E];
    int tid = threadIdx.x;
    float s[E] = {0.f, 0.f, 0.f, 0.f};
    for (int i = tid; i < B; i += 256) {
#pragma unroll
        for (int e = 0; e < E; e++) s[e] += probs[i * E + e];
    }
#pragma unroll
    for (int e = 0; e < E; e++) sm[tid * E + e] = s[e];
    __syncthreads();
    for (int st = 128; st > 0; st >>= 1) {
        if (tid < st)
#pragma unroll
            for (int e = 0; e < E; e++) sm[tid * E + e] += sm[(tid + st) * E + e];
        __syncthreads();
    }
    if (tid == 0) {
        float a = 0.f;
#pragma unroll
        for (int e = 0; e < E; e++) {
            float m = sm[e] * (1.f / B) - 1.f / E;
            a += m * m;
        }
        out[0] = a * (1.f / E);
    }
}

// ---------------- expert conv1 (3->64) + relu + maxpool2 ----------------
// Computes in fp32, stages hi/lo fp16 in smem, stores coalesced uint4 rows
// into transposed halo layout [b][pix(18x18)][ci] (rows padded to 72 halves).
#define C1_DYN (2 * 256 * ROWP * 2)   // 73728 bytes: oh + ol staging
__global__ void __launch_bounds__(256) conv1_kernel(
    const float* __restrict__ x, const float* __restrict__ c1w,
    const float* __restrict__ c1b)
{
    __shared__ float xs[CIN * 34 * 34];
    __shared__ float ws[C1 * 27];
    __shared__ float bs[C1];
    extern __shared__ char dyn1[];
    __half* oh = (__half*)dyn1;                   // [256 pix][72]
    __half* ol = oh + 256 * ROWP;

    int b   = blockIdx.x;
    int tid = threadIdx.x;
    int e   = g_bidx[b];

    for (int i = tid; i < CIN * 34 * 34; i += 256) xs[i] = 0.f;
    __syncthreads();
    const float* xb = x + (size_t)b * CIN * HW * HW;
    for (int i = tid; i < CIN * HW * HW; i += 256) {
        int ci = i >> 10, y = (i >> 5) & 31, xx = i & 31;
        xs[(ci * 34 + y + 1) * 34 + xx + 1] = xb[i];
    }
    const float* wsrc = c1w + (size_t)e * C1 * 27;
    for (int i = tid; i < C1 * 27; i += 256) ws[i] = wsrc[i];
    if (tid < C1) bs[tid] = c1b[e * C1 + tid];
    __syncthreads();

    int co   = tid >> 2;
    int quad = tid & 3;
    float w[27];
#pragma unroll
    for (int k = 0; k < 27; k++) w[k] = ws[co * 27 + k];
    float bias = bs[co];

    for (int pr = 0; pr < 4; pr++) {
        int py = quad * 4 + pr;
        int Y  = 2 * py;
        for (int px = 0; px < 16; px++) {
            int X = 2 * px;
            float a00 = bias, a01 = bias, a10 = bias, a11 = bias;
#pragma unroll
            for (int ci = 0; ci < CIN; ci++) {
                float in[4][4];
#pragma unroll
                for (int iy = 0; iy < 4; iy++)
#pragma unroll
                    for (int ix = 0; ix < 4; ix++)
                        in[iy][ix] = xs[(ci * 34 + Y + iy) * 34 + X + ix];
#pragma unroll
                for (int dy = 0; dy < 3; dy++)
#pragma unroll
                    for (int dx = 0; dx < 3; dx++) {
                        float wv = w[ci * 9 + dy * 3 + dx];
                        a00 = fmaf(in[dy][dx],     wv, a00);
                        a01 = fmaf(in[dy][dx + 1], wv, a01);
                        a10 = fmaf(in[dy + 1][dx],     wv, a10);
                        a11 = fmaf(in[dy + 1][dx + 1], wv, a11);
                    }
            }
            float m = fmaxf(fmaxf(a00, a01), fmaxf(a10, a11));
            float v = fmaxf(m, 0.f);
            __half h = __float2half_rn(v);
            int prow = py * 16 + px;
            oh[prow * ROWP + co] = h;
            ol[prow * ROWP + co] = __float2half_rn(v - __half2float(h));
        }
    }
    __syncthreads();

    // coalesced copy: 256 pix rows x 144 B per array, to halo interior
    const uint4* sh = (const uint4*)oh;    // 2304 uint4
    const uint4* sl = (const uint4*)ol;
    uint4* dh = (uint4*)(g_b1h + (size_t)b * NPIX * ROWP);
    uint4* dl = (uint4*)(g_b1l + (size_t)b * NPIX * ROWP);
    for (int i = tid; i < 2 * 2304; i += 256) {
        int arr = (i >= 2304);
        int k   = arr ? i - 2304 : i;
        int r   = k / 9, seg = k - 9 * r;
        int pix = (r / 16 + 1) * 18 + (r & 15) + 1;
        uint4 v = arr ? sl[k] : sh[k];
        (arr ? dl : dh)[pix * 9 + seg] = v;
    }
}

// ---------------- conv2: tap-decomposed HMMA GEMM ----------------
#define OFF_BH2   0
#define OFF_BL2   (NPIX * ROWP * 2)                 // 46656
#define OFF_A2    (2 * NPIX * ROWP * 2)             // 93312
#define A_BUF_SZ  (2 * C2 * ROWP * 2)               // hi+lo per buffer: 36864
#define C2_SMEM   (OFF_A2 + 2 * A_BUF_SZ)           // 167040

__global__ void __launch_bounds__(512, 1) conv2_mma_kernel(
    const float* __restrict__ c2b)
{
    extern __shared__ char smem[];
    uint32_t sb = smem_u32(smem);

    int b    = blockIdx.x;
    int tid  = threadIdx.x;
    int wid  = tid >> 5;
    int lane = tid & 31;
    int e    = g_bidx[b];

    {
        const uint32_t* srch = (const uint32_t*)(g_b1h + (size_t)b * NPIX * ROWP);
        const uint32_t* srcl = (const uint32_t*)(g_b1l + (size_t)b * NPIX * ROWP);
        uint32_t* dh = (uint32_t*)(smem + OFF_BH2);
        uint32_t* dl = (uint32_t*)(smem + OFF_BL2);
        for (int i = tid; i < NPIX * ROWP / 2; i += 512) {
            dh[i] = srch[i];
            dl[i] = srcl[i];
        }
    }

    const __half* wsrch = g_w2h + (size_t)e * 9 * C2 * C1;
    const __half* wsrcl = g_w2l + (size_t)e * 9 * C2 * C1;

    int arow = tid >> 2, aseg = tid & 3;
    auto stageA = [&](int tap, int buf) {
        const uint4* sh = (const uint4*)&wsrch[(size_t)(tap * C2 + arow) * C1 + aseg * 16];
        const uint4* sl = (const uint4*)&wsrcl[(size_t)(tap * C2 + arow) * C1 + aseg * 16];
        uint4* dh = (uint4*)(smem + OFF_A2 + buf * A_BUF_SZ + (arow * ROWP + aseg * 16) * 2);
        uint4* dl = (uint4*)(smem + OFF_A2 + buf * A_BUF_SZ + C2 * ROWP * 2
                             + (arow * ROWP + aseg * 16) * 2);
        dh[0] = sh[0]; dh[1] = sh[1];
        dl[0] = sl[0]; dl[1] = sl[1];
    };

    stageA(0, 0);
    __syncthreads();

    int warp_m  = wid >> 2;
    int warp_n  = wid & 3;
    int co_base = warp_m * 32;

    float acc[2][8][4];
#pragma unroll
    for (int mt = 0; mt < 2; mt++)
#pragma unroll
        for (int nt = 0; nt < 8; nt++)
#pragma unroll
            for (int j = 0; j < 4; j++) acc[mt][nt][j] = 0.f;

    uint32_t a_off = (uint32_t)((lane & 15) * ROWP + (lane >> 4) * 8) * 2;
    int br = lane & 7;
    int bk = ((lane >> 3) & 1) * 16;

    for (int tap = 0; tap < 9; tap++) {
        if (tap + 1 < 9) stageA(tap + 1, (tap + 1) & 1);
        int dy = tap / 3, dx = tap % 3;
        uint32_t abase_h = sb + OFF_A2 + (tap & 1) * A_BUF_SZ;
        uint32_t abase_l = abase_h + C2 * ROWP * 2;

#pragma unroll
        for (int ks = 0; ks < 4; ks++) {
            uint32_t kso = (uint32_t)(ks * 32);
            uint32_t a_h[2][4], a_l[2][4];
#pragma unroll
            for (int mt = 0; mt < 2; mt++) {
                uint32_t ra = (uint32_t)((co_base + mt * 16) * ROWP * 2) + a_off + kso;
                ldsm_x4(a_h[mt][0], a_h[mt][1], a_h[mt][2], a_h[mt][3], abase_h + ra);
                ldsm_x4(a_l[mt][0], a_l[mt][1], a_l[mt][2], a_l[mt][3], abase_l + ra);
            }
#pragma unroll
            for (int nt = 0; nt < 8; nt++) {
                int y  = warp_n * 4 + (nt >> 1);
                int x0 = (nt & 1) * 8;
                uint32_t rrow = (uint32_t)((y + dy) * 18 + x0 + dx + br);
                uint32_t rb   = rrow * (ROWP * 2) + bk + kso;
                uint32_t bh0, bh1, bl0, bl1;
                ldsm_x2(bh0, bh1, sb + OFF_BH2 + rb);
                ldsm_x2(bl0, bl1, sb + OFF_BL2 + rb);
#pragma unroll
                for (int mt = 0; mt < 2; mt++) {
                    mma16816(acc[mt][nt], a_h[mt], bh0, bh1);
                    mma16816(acc[mt][nt], a_h[mt], bl0, bl1);
                    mma16816(acc[mt][nt], a_l[mt], bh0, bh1);
                }
            }
        }
        __syncthreads();
    }

    int r  = lane >> 2;
    int c2 = lane & 3;
    float* dstb = g_buf2 + (size_t)b * FCIN;
#pragma unroll
    for (int mt = 0; mt < 2; mt++) {
#pragma unroll
        for (int rg = 0; rg < 2; rg++) {
            int co = co_base + mt * 16 + r + rg * 8;
            float bias = c2b[e * C2 + co];
#pragma unroll
            for (int q = 0; q < 4; q++) {
                int ntp = (q & 1) + (q >> 1) * 4;
                float m = fmaxf(
                    fmaxf(acc[mt][ntp][rg * 2],     acc[mt][ntp][rg * 2 + 1]),
                    fmaxf(acc[mt][ntp + 2][rg * 2], acc[mt][ntp + 2][rg * 2 + 1]));
                int py = warp_n * 2 + (ntp >> 2);
                int px = (ntp & 1) * 4 + c2;
                dstb[co * 64 + py * 8 + px] = fmaxf(m + bias, 0.f);
            }
        }
    }
}

// ---------------- expert FC: gathered mini-GEMM, f32x2 over k ----------------
#define FC_SPB 16
__global__ void __launch_bounds__(256) fc_kernel(
    const float* __restrict__ fw, const float* __restrict__ fb,
    float* __restrict__ out)
{
    int e     = blockIdx.x >> 6;
    int chunk = blockIdx.x & 63;
    int n  = g_count[e];
    int s0 = chunk * FC_SPB;
    if (s0 >= n) return;
    int m = n - s0; if (m > FC_SPB) m = FC_SPB;

    __shared__ float As[FC_SPB][128];
    __shared__ int   sidx[FC_SPB];

    int tid = threadIdx.x;
    if (tid < FC_SPB) {
        int idx = s0 + tid; if (idx >= n) idx = n - 1;
        sidx[tid] = g_list[e * B + idx];
    }
    __syncthreads();

    int sg = tid / 50;                // 0..3 (x4 samples), act if <200
    int cg = tid % 50;                // 0..49 (col pairs)
    bool act = (tid < 200);

    ull c[4][2];
#pragma unroll
    for (int s = 0; s < 4; s++) { c[s][0] = 0; c[s][1] = 0; }

    const float* w0 = fw + ((size_t)e * NC + cg * 2) * FCIN;
    const float* w1 = w0 + FCIN;

    int fr = tid >> 4;                // 0..15
    int fk = (tid & 15) * 8;          // 0..120 step 8

    for (int k0 = 0; k0 < FCIN; k0 += 128) {
        __syncthreads();
        {
            const float4* src = (const float4*)&g_buf2[(size_t)sidx[fr] * FCIN + k0 + fk];
            *(float4*)&As[fr][fk]     = src[0];
            *(float4*)&As[fr][fk + 4] = src[1];
        }
        __syncthreads();
        if (act) {
            const float* a0 = As[sg * 4];
            const float* a1 = As[sg * 4 + 1];
            const float* a2 = As[sg * 4 + 2];
            const float* a3 = As[sg * 4 + 3];
#pragma unroll 8
            for (int kk = 0; kk < 128; kk += 2) {
                ull wa = *(const ull*)(w0 + k0 + kk);
                ull wb = *(const ull*)(w1 + k0 + kk);
                ull v0 = *(const ull*)(a0 + kk);
                ull v1 = *(const ull*)(a1 + kk);
                ull v2 = *(const ull*)(a2 + kk);
                ull v3 = *(const ull*)(a3 + kk);
                c[0][0] = ffma2(v0, wa, c[0][0]); c[0][1] = ffma2(v0, wb, c[0][1]);
                c[1][0] = ffma2(v1, wa, c[1][0]); c[1][1] = ffma2(v1, wb, c[1][1]);
                c[2][0] = ffma2(v2, wa, c[2][0]); c[2][1] = ffma2(v2, wb, c[2][1]);
                c[3][0] = ffma2(v3, wa, c[3][0]); c[3][1] = ffma2(v3, wb, c[3][1]);
            }
        }
    }

    if (act) {
#pragma unroll
        for (int s = 0; s < 4; s++) {
            int rr = sg * 4 + s;
            if (rr < m) {
                int smp = sidx[rr];
                float scale = g_bw[smp];
                float lo, hi;
#pragma unroll
                for (int cj = 0; cj < 2; cj++) {
                    upk(c[s][cj], lo, hi);
                    int col = cg * 2 + cj;
                    out[(size_t)smp * NC + col] =
                        (lo + hi + fb[e * NC + col]) * scale;
                }
            }
        }
    }
}

// ---------------- launch ----------------
extern "C" void kernel_launch(void* const* d_in, const int* in_sizes, int n_in,
                              void* d_out, int out_size)
{
    const float* x       = (const float*)d_in[0];
    const float* gate_cw = (const float*)d_in[1];
    const float* gate_cb = (const float*)d_in[2];
    const float* gate_fw = (const float*)d_in[3];
    const float* gate_fb = (const float*)d_in[4];
    const float* e_c1w   = (const float*)d_in[5];
    const float* e_c1b   = (const float*)d_in[6];
    const float* e_c2w   = (const float*)d_in[7];
    const float* e_c2b   = (const float*)d_in[8];
    const float* e_fw    = (const float*)d_in[9];
    const float* e_fb    = (const float*)d_in[10];
    float* out = (float*)d_out;

    cudaFuncSetAttribute(conv2_mma_kernel,
                         cudaFuncAttributeMaxDynamicSharedMemorySize, C2_SMEM);
    cudaFuncSetAttribute(conv1_kernel,
                         cudaFuncAttributeMaxDynamicSharedMemorySize, C1_DYN);

    prep_w2_kernel<<<(E * 9 * C2 * C1 + 255) / 256, 256>>>(e_c2w);
    gate_conv_kernel<<<B, 256>>>(x, gate_cw, gate_cb);
    router_kernel<<<B / 256, 256>>>(gate_fw, gate_fb, out + OUT_PROBS_OFF);
    aux_kernel<<<1, 256>>>(out + OUT_PROBS_OFF, out + OUT_AUX_OFF);
    conv1_kernel<<<B, 256, C1_DYN>>>(x, e_c1w, e_c1b);
    conv2_mma_kernel<<<B, 512, C2_SMEM>>>(e_c2b);
    fc_kernel<<<E * 64, 256>>>(e_fw, e_fb, out);
}

// round 8
// speedup vs baseline: 1.0312x; 1.0312x over previous
#include <cuda_runtime.h>
#include <cuda_fp16.h>
#include <math.h>
#include <cstdint>

// ---------------- problem constants ----------------
#define B     1024
#define CIN   3
#define HW    32
#define GC    16
#define E     4
#define C1    64
#define C2    128
#define NC    100
#define FCIN  8192      // 128*8*8

#define NPIX  324       // 18*18 haloed conv1 output grid
#define ROWP  72        // padded row length (halves); 144B stride

#define OUT_PROBS_OFF (B*NC)
#define OUT_AUX_OFF   (B*NC + B*E)

typedef unsigned long long ull;

// ---- f32x2 helpers ----
__device__ __forceinline__ ull ffma2(ull a, ull b, ull c) {
    ull d;
    asm("fma.rn.f32x2 %0, %1, %2, %3;" : "=l"(d) : "l"(a), "l"(b), "l"(c));
    return d;
}
__device__ __forceinline__ void upk(ull v, float& lo, float& hi) {
    asm("mov.b64 {%0, %1}, %2;" : "=f"(lo), "=f"(hi) : "l"(v));
}

__device__ __forceinline__ uint32_t smem_u32(const void* p) {
    uint32_t a;
    asm("{ .reg .u64 t; cvta.to.shared.u64 t, %1; cvt.u32.u64 %0, t; }"
        : "=r"(a) : "l"(p));
    return a;
}
__device__ __forceinline__ void ldsm_x4(uint32_t& r0, uint32_t& r1,
                                        uint32_t& r2, uint32_t& r3, uint32_t a) {
    asm volatile("ldmatrix.sync.aligned.m8n8.x4.shared.b16 {%0,%1,%2,%3}, [%4];"
                 : "=r"(r0), "=r"(r1), "=r"(r2), "=r"(r3) : "r"(a));
}
__device__ __forceinline__ void mma16816(float* d, const uint32_t* a,
                                         uint32_t b0, uint32_t b1) {
    asm volatile(
        "mma.sync.aligned.m16n8k16.row.col.f32.f16.f16.f32 "
        "{%0,%1,%2,%3}, {%4,%5,%6,%7}, {%8,%9}, {%0,%1,%2,%3};"
        : "+f"(d[0]), "+f"(d[1]), "+f"(d[2]), "+f"(d[3])
        : "r"(a[0]), "r"(a[1]), "r"(a[2]), "r"(a[3]), "r"(b0), "r"(b1));
}

// ---------------- device scratch (zero-initialized; halo/pad cells stay 0) ----
__device__ __half g_b1h[(size_t)B * NPIX * ROWP];   // conv1 out hi, [b][pix][ci]
__device__ __half g_b1l[(size_t)B * NPIX * ROWP];   // conv1 out lo
__device__ float  g_buf2[(size_t)B * C2 * 8 * 8];   // conv2+pool out
__device__ float  g_gpool[B * GC];
__device__ int    g_bidx[B];
__device__ float  g_bw[B];
__device__ int    g_list[E * B];
__device__ int    g_count[E];
__device__ __half g_w2h[(size_t)E * 9 * C2 * C1];   // [e][tap][co][ci]
__device__ __half g_w2l[(size_t)E * 9 * C2 * C1];

// ---------------- split + transpose conv2 weights; also zero counters ------
__global__ void prep_w2_kernel(const float* __restrict__ c2w) {
    int i = blockIdx.x * blockDim.x + threadIdx.x;
    if (blockIdx.x == 0 && threadIdx.x < E) g_count[threadIdx.x] = 0;
    if (i >= E * 9 * C2 * C1) return;
    int ci   = i & 63;
    int co   = (i >> 6) & 127;
    int rest = i >> 13;            // e*9 + tap
    int tap  = rest % 9;
    int e    = rest / 9;
    float v = c2w[(((size_t)(e * C2 + co)) * C1 + ci) * 9 + tap];
    __half h = __float2half_rn(v);
    g_w2h[i] = h;
    g_w2l[i] = __float2half_rn(v - __half2float(h));
}

// ---------------- gating conv (3->16) + relu + GAP ----------------
__global__ void __launch_bounds__(256) gate_conv_kernel(
    const float* __restrict__ x, const float* __restrict__ gcw,
    const float* __restrict__ gcb)
{
    __shared__ float xs[CIN * 34 * 34];
    __shared__ float wg[GC * 27];
    __shared__ float gb[GC];
    __shared__ float red[256];

    int b   = blockIdx.x;
    int tid = threadIdx.x;

    for (int i = tid; i < CIN * 34 * 34; i += 256) xs[i] = 0.f;
    __syncthreads();
    const float* xb = x + (size_t)b * CIN * HW * HW;
    for (int i = tid; i < CIN * HW * HW; i += 256) {
        int ci = i >> 10, y = (i >> 5) & 31, xx = i & 31;
        xs[(ci * 34 + y + 1) * 34 + xx + 1] = xb[i];
    }
    for (int i = tid; i < GC * 27; i += 256) wg[i] = gcw[i];
    if (tid < GC) gb[tid] = gcb[tid];
    __syncthreads();

    int co = tid >> 4;
    int ln = tid & 15;
    float w[27];
#pragma unroll
    for (int k = 0; k < 27; k++) w[k] = wg[co * 27 + k];
    float bias = gb[co];

    float s = 0.f;
    for (int p = ln; p < HW * HW; p += 16) {
        int y = p >> 5, xx = p & 31;
        float v = bias;
#pragma unroll
        for (int ci = 0; ci < CIN; ci++)
#pragma unroll
            for (int dy = 0; dy < 3; dy++)
#pragma unroll
                for (int dx = 0; dx < 3; dx++)
                    v = fmaf(xs[(ci * 34 + y + dy) * 34 + xx + dx],
                             w[ci * 9 + dy * 3 + dx], v);
        s += fmaxf(v, 0.f);
    }
    red[tid] = s;
    __syncthreads();
    if (ln == 0) {
        float t = 0.f;
#pragma unroll
        for (int j = 0; j < 16; j++) t += red[co * 16 + j];
        g_gpool[b * GC + co] = t * (1.f / (HW * HW));
    }
}

// ---------------- router ----------------
__global__ void router_kernel(const float* __restrict__ gfw,
                              const float* __restrict__ gfb,
                              float* __restrict__ out_probs)
{
    int b = blockIdx.x * blockDim.x + threadIdx.x;
    if (b >= B) return;
    float gp[GC];
#pragma unroll
    for (int k = 0; k < GC; k++) gp[k] = g_gpool[b * GC + k];

    float lg[E];
#pragma unroll
    for (int e = 0; e < E; e++) {
        float s = gfb[e];
#pragma unroll
        for (int k = 0; k < GC; k++) s = fmaf(gp[k], gfw[e * GC + k], s);
        lg[e] = s;
    }
    float mx = lg[0];
#pragma unroll
    for (int e = 1; e < E; e++) mx = fmaxf(mx, lg[e]);
    float ex[E], se = 0.f;
#pragma unroll
    for (int e = 0; e < E; e++) { ex[e] = expf(lg[e] - mx); se += ex[e]; }
    float inv = 1.f / se;

    float bw = -1.f; int bi = 0;
#pragma unroll
    for (int e = 0; e < E; e++) {
        float p = ex[e] * inv;
        out_probs[b * E + e] = p;
        if (p > bw) { bw = p; bi = e; }
    }
    g_bidx[b] = bi;
    g_bw[b]   = bw;
    int pos = atomicAdd(&g_count[bi], 1);
    g_list[bi * B + pos] = b;
}

// ---------------- aux loss ----------------
__global__ void aux_kernel(const float* __restrict__ probs, float* __restrict__ out)
{
    __shared__ float sm[256 * E];
    int tid = threadIdx.x;
    float s[E] = {0.f, 0.f, 0.f, 0.f};
    for (int i = tid; i < B; i += 256) {
#pragma unroll
        for (int e = 0; e < E; e++) s[e] += probs[i * E + e];
    }
#pragma unroll
    for (int e = 0; e < E; e++) sm[tid * E + e] = s[e];
    __syncthreads();
    for (int st = 128; st > 0; st >>= 1) {
        if (tid < st)
#pragma unroll
            for (int e = 0; e < E; e++) sm[tid * E + e] += sm[(tid + st) * E + e];
        __syncthreads();
    }
    if (tid == 0) {
        float a = 0.f;
#pragma unroll
        for (int e = 0; e < E; e++) {
            float m = sm[e] * (1.f / B) - 1.f / E;
            a += m * m;
        }
        out[0] = a * (1.f / E);
    }
}

// ---------------- expert conv1 (3->64) + relu + maxpool2 ----------------
// writes hi/lo fp16 in transposed halo layout [b][pix(18x18)][ci] (rows padded to 72)
__global__ void __launch_bounds__(256) conv1_kernel(
    const float* __restrict__ x, const float* __restrict__ c1w,
    const float* __restrict__ c1b)
{
    __shared__ float xs[CIN * 34 * 34];
    __shared__ float ws[C1 * 27];
    __shared__ float bs[C1];

    int b   = blockIdx.x;
    int tid = threadIdx.x;
    int e   = g_bidx[b];

    for (int i = tid; i < CIN * 34 * 34; i += 256) xs[i] = 0.f;
    __syncthreads();
    const float* xb = x + (size_t)b * CIN * HW * HW;
    for (int i = tid; i < CIN * HW * HW; i += 256) {
        int ci = i >> 10, y = (i >> 5) & 31, xx = i & 31;
        xs[(ci * 34 + y + 1) * 34 + xx + 1] = xb[i];
    }
    const float* wsrc = c1w + (size_t)e * C1 * 27;
    for (int i = tid; i < C1 * 27; i += 256) ws[i] = wsrc[i];
    if (tid < C1) bs[tid] = c1b[e * C1 + tid];
    __syncthreads();

    int co   = tid >> 2;
    int quad = tid & 3;
    float w[27];
#pragma unroll
    for (int k = 0; k < 27; k++) w[k] = ws[co * 27 + k];
    float bias = bs[co];

    __half* dsth = g_b1h + (size_t)b * NPIX * ROWP;
    __half* dstl = g_b1l + (size_t)b * NPIX * ROWP;

    for (int pr = 0; pr < 4; pr++) {
        int py = quad * 4 + pr;
        int Y  = 2 * py;
        for (int px = 0; px < 16; px++) {
            int X = 2 * px;
            float a00 = bias, a01 = bias, a10 = bias, a11 = bias;
#pragma unroll
            for (int ci = 0; ci < CIN; ci++) {
                float in[4][4];
#pragma unroll
                for (int iy = 0; iy < 4; iy++)
#pragma unroll
                    for (int ix = 0; ix < 4; ix++)
                        in[iy][ix] = xs[(ci * 34 + Y + iy) * 34 + X + ix];
#pragma unroll
                for (int dy = 0; dy < 3; dy++)
#pragma unroll
                    for (int dx = 0; dx < 3; dx++) {
                        float wv = w[ci * 9 + dy * 3 + dx];
                        a00 = fmaf(in[dy][dx],     wv, a00);
                        a01 = fmaf(in[dy][dx + 1], wv, a01);
                        a10 = fmaf(in[dy + 1][dx],     wv, a10);
                        a11 = fmaf(in[dy + 1][dx + 1], wv, a11);
                    }
            }
            float m = fmaxf(fmaxf(a00, a01), fmaxf(a10, a11));
            float v = fmaxf(m, 0.f);
            __half h = __float2half_rn(v);
            int pix = (py + 1) * 18 + (px + 1);
            dsth[pix * ROWP + co] = h;
            dstl[pix * ROWP + co] = __float2half_rn(v - __half2float(h));
        }
    }
}

// ---------------- conv2: tap-decomposed HMMA GEMM (B loaded via x4 pairs) ----
#define OFF_BH2   0
#define OFF_BL2   (NPIX * ROWP * 2)                 // 46656
#define OFF_A2    (2 * NPIX * ROWP * 2)             // 93312
#define A_BUF_SZ  (2 * C2 * ROWP * 2)               // hi+lo per buffer: 36864
#define C2_SMEM   (OFF_A2 + 2 * A_BUF_SZ)           // 167040

__global__ void __launch_bounds__(512, 1) conv2_mma_kernel(
    const float* __restrict__ c2b)
{
    extern __shared__ char smem[];
    uint32_t sb = smem_u32(smem);

    int b    = blockIdx.x;
    int tid  = threadIdx.x;
    int wid  = tid >> 5;
    int lane = tid & 31;
    int e    = g_bidx[b];

    {
        const uint32_t* srch = (const uint32_t*)(g_b1h + (size_t)b * NPIX * ROWP);
        const uint32_t* srcl = (const uint32_t*)(g_b1l + (size_t)b * NPIX * ROWP);
        uint32_t* dh = (uint32_t*)(smem + OFF_BH2);
        uint32_t* dl = (uint32_t*)(smem + OFF_BL2);
        for (int i = tid; i < NPIX * ROWP / 2; i += 512) {
            dh[i] = srch[i];
            dl[i] = srcl[i];
        }
    }

    const __half* wsrch = g_w2h + (size_t)e * 9 * C2 * C1;
    const __half* wsrcl = g_w2l + (size_t)e * 9 * C2 * C1;

    int arow = tid >> 2, aseg = tid & 3;
    auto stageA = [&](int tap, int buf) {
        const uint4* sh = (const uint4*)&wsrch[(size_t)(tap * C2 + arow) * C1 + aseg * 16];
        const uint4* sl = (const uint4*)&wsrcl[(size_t)(tap * C2 + arow) * C1 + aseg * 16];
        uint4* dh = (uint4*)(smem + OFF_A2 + buf * A_BUF_SZ + (arow * ROWP + aseg * 16) * 2);
        uint4* dl = (uint4*)(smem + OFF_A2 + buf * A_BUF_SZ + C2 * ROWP * 2
                             + (arow * ROWP + aseg * 16) * 2);
        dh[0] = sh[0]; dh[1] = sh[1];
        dl[0] = sl[0]; dl[1] = sl[1];
    };

    stageA(0, 0);
    __syncthreads();

    int warp_m  = wid >> 2;
    int warp_n  = wid & 3;
    int co_base = warp_m * 32;

    float acc[2][8][4];
#pragma unroll
    for (int mt = 0; mt < 2; mt++)
#pragma unroll
        for (int nt = 0; nt < 8; nt++)
#pragma unroll
            for (int j = 0; j < 4; j++) acc[mt][nt][j] = 0.f;

    uint32_t a_off = (uint32_t)((lane & 15) * ROWP + (lane >> 4) * 8) * 2;
    // B x4 addressing: 16 consecutive halo rows per nt-pair
    //   lanes 0-7:  rows 0-7,  k bytes 0-15   (matrix 0 -> even nt, b0)
    //   lanes 8-15: rows 0-7,  k bytes 16-31  (matrix 1 -> even nt, b1)
    //   lanes 16-23: rows 8-15, k bytes 0-15  (matrix 2 -> odd nt, b0)
    //   lanes 24-31: rows 8-15, k bytes 16-31 (matrix 3 -> odd nt, b1)
    uint32_t b_off = (uint32_t)(((lane & 7) + ((lane >> 4) << 3)) * ROWP * 2)
                   + (uint32_t)(((lane >> 3) & 1) * 16);

    for (int tap = 0; tap < 9; tap++) {
        if (tap + 1 < 9) stageA(tap + 1, (tap + 1) & 1);
        int dy = tap / 3, dx = tap % 3;
        uint32_t abase_h = sb + OFF_A2 + (tap & 1) * A_BUF_SZ;
        uint32_t abase_l = abase_h + C2 * ROWP * 2;

#pragma unroll
        for (int ks = 0; ks < 4; ks++) {
            uint32_t kso = (uint32_t)(ks * 32);
            uint32_t a_h[2][4], a_l[2][4];
#pragma unroll
            for (int mt = 0; mt < 2; mt++) {
                uint32_t ra = (uint32_t)((co_base + mt * 16) * ROWP * 2) + a_off + kso;
                ldsm_x4(a_h[mt][0], a_h[mt][1], a_h[mt][2], a_h[mt][3], abase_h + ra);
                ldsm_x4(a_l[mt][0], a_l[mt][1], a_l[mt][2], a_l[mt][3], abase_l + ra);
            }
#pragma unroll
            for (int ntp = 0; ntp < 4; ntp++) {
                int y  = warp_n * 4 + ntp;
                uint32_t rrow = (uint32_t)((y + dy) * 18 + dx);
                uint32_t rb   = rrow * (ROWP * 2) + b_off + kso;
                uint32_t bh0, bh1, bh2, bh3, bl0, bl1, bl2, bl3;
                ldsm_x4(bh0, bh1, bh2, bh3, sb + OFF_BH2 + rb);
                ldsm_x4(bl0, bl1, bl2, bl3, sb + OFF_BL2 + rb);
                int nt0 = 2 * ntp, nt1 = 2 * ntp + 1;
#pragma unroll
                for (int mt = 0; mt < 2; mt++) {
                    mma16816(acc[mt][nt0], a_h[mt], bh0, bh1);
                    mma16816(acc[mt][nt0], a_h[mt], bl0, bl1);
                    mma16816(acc[mt][nt0], a_l[mt], bh0, bh1);
                    mma16816(acc[mt][nt1], a_h[mt], bh2, bh3);
                    mma16816(acc[mt][nt1], a_h[mt], bl2, bl3);
                    mma16816(acc[mt][nt1], a_l[mt], bh2, bh3);
                }
            }
        }
        __syncthreads();
    }

    int r  = lane >> 2;
    int c2 = lane & 3;
    float* dstb = g_buf2 + (size_t)b * FCIN;
#pragma unroll
    for (int mt = 0; mt < 2; mt++) {
#pragma unroll
        for (int rg = 0; rg < 2; rg++) {
            int co = co_base + mt * 16 + r + rg * 8;
            float bias = c2b[e * C2 + co];
#pragma unroll
            for (int q = 0; q < 4; q++) {
                int ntp = (q & 1) + (q >> 1) * 4;   // 0,1,4,5
                float m = fmaxf(
                    fmaxf(acc[mt][ntp][rg * 2],     acc[mt][ntp][rg * 2 + 1]),
                    fmaxf(acc[mt][ntp + 2][rg * 2], acc[mt][ntp + 2][rg * 2 + 1]));
                int py = warp_n * 2 + (ntp >> 2);
                int px = (ntp & 1) * 4 + c2;
                dstb[co * 64 + py * 8 + px] = fmaxf(m + bias, 0.f);
            }
        }
    }
}

// ---------------- expert FC: gathered mini-GEMM, f32x2 over k ----------------
#define FC_SPB 8
__global__ void __launch_bounds__(256) fc_kernel(
    const float* __restrict__ fw, const float* __restrict__ fb,
    float* __restrict__ out)
{
    int e     = blockIdx.x >> 7;
    int chunk = blockIdx.x & 127;
    int n  = g_count[e];
    int s0 = chunk * FC_SPB;
    if (s0 >= n) return;
    int m = n - s0; if (m > FC_SPB) m = FC_SPB;

    __shared__ float As[FC_SPB][128];
    __shared__ int   sidx[FC_SPB];

    int tid = threadIdx.x;
    if (tid < FC_SPB) {
        sidx[tid] = g_list[e * B + ((tid < m) ? (s0 + tid) : s0)];
    }
    __syncthreads();

    int sg = tid / 50;
    int cg = tid % 50;
    bool act = (tid < 200);

    ull c00 = 0, c01 = 0, c10 = 0, c11 = 0;
    const float* w0 = fw + ((size_t)e * NC + cg * 2) * FCIN;
    const float* w1 = w0 + FCIN;

    int fr  = tid >> 5;
    int fk4 = (tid & 31) * 4;

    for (int k0 = 0; k0 < FCIN; k0 += 128) {
        __syncthreads();
        *(float4*)&As[fr][fk4] =
            *(const float4*)&g_buf2[(size_t)sidx[fr] * FCIN + k0 + fk4];
        __syncthreads();
        if (act) {
            const float* a0 = As[sg * 2];
            const float* a1 = As[sg * 2 + 1];
#pragma unroll 16
            for (int kk = 0; kk < 128; kk += 2) {
                ull wa = *(const ull*)(w0 + k0 + kk);
                ull wb = *(const ull*)(w1 + k0 + kk);
                ull v0 = *(const ull*)(a0 + kk);
                ull v1 = *(const ull*)(a1 + kk);
                c00 = ffma2(v0, wa, c00);
                c01 = ffma2(v0, wb, c01);
                c10 = ffma2(v1, wa, c10);
                c11 = ffma2(v1, wb, c11);
            }
        }
    }

    if (act) {
        float lo, hi;
        float a[2][2];
        upk(c00, lo, hi); a[0][0] = lo + hi;
        upk(c01, lo, hi); a[0][1] = lo + hi;
        upk(c10, lo, hi); a[1][0] = lo + hi;
        upk(c11, lo, hi); a[1][1] = lo + hi;
#pragma unroll
        for (int si = 0; si < 2; si++) {
            int rr = sg * 2 + si;
            if (rr < m) {
                int s = sidx[rr];
                float scale = g_bw[s];
#pragma unroll
                for (int cj = 0; cj < 2; cj++) {
                    int c = cg * 2 + cj;
                    out[(size_t)s * NC + c] = (a[si][cj] + fb[e * NC + c]) * scale;
                }
            }
        }
    }
}

// ---------------- launch ----------------
extern "C" void kernel_launch(void* const* d_in, const int* in_sizes, int n_in,
                              void* d_out, int out_size)
{
    const float* x       = (const float*)d_in[0];
    const float* gate_cw = (const float*)d_in[1];
    const float* gate_cb = (const float*)d_in[2];
    const float* gate_fw = (const float*)d_in[3];
    const float* gate_fb = (const float*)d_in[4];
    const float* e_c1w   = (const float*)d_in[5];
    const float* e_c1b   = (const float*)d_in[6];
    const float* e_c2w   = (const float*)d_in[7];
    const float* e_c2b   = (const float*)d_in[8];
    const float* e_fw    = (const float*)d_in[9];
    const float* e_fb    = (const float*)d_in[10];
    float* out = (float*)d_out;

    cudaFuncSetAttribute(conv2_mma_kernel,
                         cudaFuncAttributeMaxDynamicSharedMemorySize, C2_SMEM);

    prep_w2_kernel<<<(E * 9 * C2 * C1 + 255) / 256, 256>>>(e_c2w);
    gate_conv_kernel<<<B, 256>>>(x, gate_cw, gate_cb);
    router_kernel<<<B / 256, 256>>>(gate_fw, gate_fb, out + OUT_PROBS_OFF);
    aux_kernel<<<1, 256>>>(out + OUT_PROBS_OFF, out + OUT_AUX_OFF);
    conv1_kernel<<<B, 256>>>(x, e_c1w, e_c1b);
    conv2_mma_kernel<<<B, 512, C2_SMEM>>>(e_c2b);
    fc_kernel<<<E * 128, 256>>>(e_fw, e_fb, out);
}

// round 9
// speedup vs baseline: 1.1262x; 1.0922x over previous
#include <cuda_runtime.h>
#include <cuda_fp16.h>
#include <math.h>
#include <cstdint>

// ---------------- problem constants ----------------
#define B     1024
#define CIN   3
#define HW    32
#define GC    16
#define E     4
#define C1    64
#define C2    128
#define NC    100
#define FCIN  8192      // 128*8*8

#define NPIX  324       // 18*18 haloed conv1 output grid
#define ROWP  72        // padded row length (halves); 144B stride

#define OUT_PROBS_OFF (B*NC)
#define OUT_AUX_OFF   (B*NC + B*E)

typedef unsigned long long ull;

// ---- f32x2 helpers ----
__device__ __forceinline__ ull ffma2(ull a, ull b, ull c) {
    ull d;
    asm("fma.rn.f32x2 %0, %1, %2, %3;" : "=l"(d) : "l"(a), "l"(b), "l"(c));
    return d;
}
__device__ __forceinline__ ull pk(float lo, float hi) {
    ull r;
    asm("mov.b64 %0, {%1, %2};" : "=l"(r) : "f"(lo), "f"(hi));
    return r;
}
__device__ __forceinline__ void upk(ull v, float& lo, float& hi) {
    asm("mov.b64 {%0, %1}, %2;" : "=f"(lo), "=f"(hi) : "l"(v));
}

__device__ __forceinline__ uint32_t smem_u32(const void* p) {
    uint32_t a;
    asm("{ .reg .u64 t; cvta.to.shared.u64 t, %1; cvt.u32.u64 %0, t; }"
        : "=r"(a) : "l"(p));
    return a;
}
__device__ __forceinline__ void ldsm_x4(uint32_t& r0, uint32_t& r1,
                                        uint32_t& r2, uint32_t& r3, uint32_t a) {
    asm volatile("ldmatrix.sync.aligned.m8n8.x4.shared.b16 {%0,%1,%2,%3}, [%4];"
                 : "=r"(r0), "=r"(r1), "=r"(r2), "=r"(r3) : "r"(a));
}
__device__ __forceinline__ void mma16816(float* d, const uint32_t* a,
                                         uint32_t b0, uint32_t b1) {
    asm volatile(
        "mma.sync.aligned.m16n8k16.row.col.f32.f16.f16.f32 "
        "{%0,%1,%2,%3}, {%4,%5,%6,%7}, {%8,%9}, {%0,%1,%2,%3};"
        : "+f"(d[0]), "+f"(d[1]), "+f"(d[2]), "+f"(d[3])
        : "r"(a[0]), "r"(a[1]), "r"(a[2]), "r"(a[3]), "r"(b0), "r"(b1));
}

// ---------------- device scratch ----------------
__device__ float  g_buf2[(size_t)B * C2 * 8 * 8];   // conv2+pool out
__device__ float  g_gpool[B * GC];
__device__ int    g_bidx[B];
__device__ float  g_bw[B];
__device__ int    g_list[E * B];
__device__ int    g_count[E];
__device__ __half g_w2h[(size_t)E * 9 * C2 * C1];   // [e][tap][co][ci]
__device__ __half g_w2l[(size_t)E * 9 * C2 * C1];

// ---------------- split + transpose conv2 weights; also zero counters ------
__global__ void prep_w2_kernel(const float* __restrict__ c2w) {
    int i = blockIdx.x * blockDim.x + threadIdx.x;
    if (blockIdx.x == 0 && threadIdx.x < E) g_count[threadIdx.x] = 0;
    if (i >= E * 9 * C2 * C1) return;
    int ci   = i & 63;
    int co   = (i >> 6) & 127;
    int rest = i >> 13;            // e*9 + tap
    int tap  = rest % 9;
    int e    = rest / 9;
    float v = c2w[(((size_t)(e * C2 + co)) * C1 + ci) * 9 + tap];
    __half h = __float2half_rn(v);
    g_w2h[i] = h;
    g_w2l[i] = __float2half_rn(v - __half2float(h));
}

// ---------------- gating conv (3->16) + relu + GAP ----------------
__global__ void __launch_bounds__(256) gate_conv_kernel(
    const float* __restrict__ x, const float* __restrict__ gcw,
    const float* __restrict__ gcb)
{
    __shared__ float xs[CIN * 34 * 34];
    __shared__ float wg[GC * 27];
    __shared__ float gb[GC];
    __shared__ float red[256];

    int b   = blockIdx.x;
    int tid = threadIdx.x;

    for (int i = tid; i < CIN * 34 * 34; i += 256) xs[i] = 0.f;
    __syncthreads();
    const float* xb = x + (size_t)b * CIN * HW * HW;
    for (int i = tid; i < CIN * HW * HW; i += 256) {
        int ci = i >> 10, y = (i >> 5) & 31, xx = i & 31;
        xs[(ci * 34 + y + 1) * 34 + xx + 1] = xb[i];
    }
    for (int i = tid; i < GC * 27; i += 256) wg[i] = gcw[i];
    if (tid < GC) gb[tid] = gcb[tid];
    __syncthreads();

    int co = tid >> 4;
    int ln = tid & 15;
    float w[27];
#pragma unroll
    for (int k = 0; k < 27; k++) w[k] = wg[co * 27 + k];
    float bias = gb[co];

    float s = 0.f;
    for (int p = ln; p < HW * HW; p += 16) {
        int y = p >> 5, xx = p & 31;
        float v = bias;
#pragma unroll
        for (int ci = 0; ci < CIN; ci++)
#pragma unroll
            for (int dy = 0; dy < 3; dy++)
#pragma unroll
                for (int dx = 0; dx < 3; dx++)
                    v = fmaf(xs[(ci * 34 + y + dy) * 34 + xx + dx],
                             w[ci * 9 + dy * 3 + dx], v);
        s += fmaxf(v, 0.f);
    }
    red[tid] = s;
    __syncthreads();
    if (ln == 0) {
        float t = 0.f;
#pragma unroll
        for (int j = 0; j < 16; j++) t += red[co * 16 + j];
        g_gpool[b * GC + co] = t * (1.f / (HW * HW));
    }
}

// ---------------- router ----------------
__global__ void router_kernel(const float* __restrict__ gfw,
                              const float* __restrict__ gfb,
                              float* __restrict__ out_probs)
{
    int b = blockIdx.x * blockDim.x + threadIdx.x;
    if (b >= B) return;
    float gp[GC];
#pragma unroll
    for (int k = 0; k < GC; k++) gp[k] = g_gpool[b * GC + k];

    float lg[E];
#pragma unroll
    for (int e = 0; e < E; e++) {
        float s = gfb[e];
#pragma unroll
        for (int k = 0; k < GC; k++) s = fmaf(gp[k], gfw[e * GC + k], s);
        lg[e] = s;
    }
    float mx = lg[0];
#pragma unroll
    for (int e = 1; e < E; e++) mx = fmaxf(mx, lg[e]);
    float ex[E], se = 0.f;
#pragma unroll
    for (int e = 0; e < E; e++) { ex[e] = expf(lg[e] - mx); se += ex[e]; }
    float inv = 1.f / se;

    float bw = -1.f; int bi = 0;
#pragma unroll
    for (int e = 0; e < E; e++) {
        float p = ex[e] * inv;
        out_probs[b * E + e] = p;
        if (p > bw) { bw = p; bi = e; }
    }
    g_bidx[b] = bi;
    g_bw[b]   = bw;
    int pos = atomicAdd(&g_count[bi], 1);
    g_list[bi * B + pos] = b;
}

// ---------------- aux loss ----------------
__global__ void aux_kernel(const float* __restrict__ probs, float* __restrict__ out)
{
    __shared__ float sm[256 * E];
    int tid = threadIdx.x;
    float s[E] = {0.f, 0.f, 0.f, 0.f};
    for (int i = tid; i < B; i += 256) {
#pragma unroll
        for (int e = 0; e < E; e++) s[e] += probs[i * E + e];
    }
#pragma unroll
    for (int e = 0; e < E; e++) sm[tid * E + e] = s[e];
    __syncthreads();
    for (int st = 128; st > 0; st >>= 1) {
        if (tid < st)
#pragma unroll
            for (int e = 0; e < E; e++) sm[tid * E + e] += sm[(tid + st) * E + e];
        __syncthreads();
    }
    if (tid == 0) {
        float a = 0.f;
#pragma unroll
        for (int e = 0; e < E; e++) {
            float m = sm[e] * (1.f / B) - 1.f / E;
            a += m * m;
        }
        out[0] = a * (1.f / E);
    }
}

// ---------------- fused conv1 + conv2 (tap-decomposed HMMA) ----------------
// Stage 1 (conv1, FFMA2): 3->64 conv + relu + maxpool2, pooled output written
//   as hi/lo fp16 directly into conv2's smem B arrays at [pix(18x18)][ci].
// Stage 2 (conv2, HMMA): D[128co,256px] = sum_tap W_tap[128,64]@In_shift^T, x3 split.
#define OFF_BH2   0
#define OFF_BL2   (NPIX * ROWP * 2)                 // 46656
#define OFF_A2    (2 * NPIX * ROWP * 2)             // 93312 (xs aliases here)
#define A_BUF_SZ  (2 * C2 * ROWP * 2)               // hi+lo per buffer: 36864
#define C2_SMEM   (OFF_A2 + 2 * A_BUF_SZ)           // 167040

__global__ void __launch_bounds__(512, 1) conv12_fused_kernel(
    const float* __restrict__ x, const float* __restrict__ c1w,
    const float* __restrict__ c1b, const float* __restrict__ c2b)
{
    extern __shared__ char smem[];
    __shared__ float ws[C1 * 27];
    __shared__ float bs[C1];
    uint32_t sb = smem_u32(smem);

    int b    = blockIdx.x;
    int tid  = threadIdx.x;
    int wid  = tid >> 5;
    int lane = tid & 31;
    int e    = g_bidx[b];

    float* xs = (float*)(smem + OFF_A2);    // 3*34*34 floats, dies before stageA

    // ---- zero B arrays (halo must be 0) + xs halo; load x, conv1 weights ----
    {
        uint32_t* bz = (uint32_t*)(smem + OFF_BH2);
        for (int i = tid; i < NPIX * ROWP; i += 512) bz[i] = 0;  // BH+BL
        for (int i = tid; i < CIN * 34 * 34; i += 512) xs[i] = 0.f;
    }
    __syncthreads();
    {
        const float* xb = x + (size_t)b * CIN * HW * HW;
        for (int i = tid; i < CIN * HW * HW; i += 512) {
            int ci = i >> 10, y = (i >> 5) & 31, xx = i & 31;
            xs[(ci * 34 + y + 1) * 34 + xx + 1] = xb[i];
        }
        const float* wsrc = c1w + (size_t)e * C1 * 27;
        for (int i = tid; i < C1 * 27; i += 512) ws[i] = wsrc[i];
        if (tid < C1) bs[tid] = c1b[e * C1 + tid];
    }
    __syncthreads();

    // ---- conv1: FFMA2 over x-pairs; write pooled hi/lo into B arrays ----
    {
        int co  = tid >> 3;      // 0..63
        int oct = tid & 7;       // 0..7 -> 2 pooled rows each
        float wr[27];
#pragma unroll
        for (int k = 0; k < 27; k++) wr[k] = ws[co * 27 + k];
        float bias = bs[co];
        ull bias2 = pk(bias, bias);
        __half* BHp = (__half*)(smem + OFF_BH2);
        __half* BLp = (__half*)(smem + OFF_BL2);

        for (int pr = 0; pr < 2; pr++) {
            int py = oct * 2 + pr;
            int Y  = 2 * py;
            for (int pg = 0; pg < 2; pg++) {
                ull acc0[8], acc1[8];
#pragma unroll
                for (int j = 0; j < 8; j++) { acc0[j] = bias2; acc1[j] = bias2; }
#pragma unroll
                for (int ci = 0; ci < CIN; ci++) {
                    ull w2[9];
#pragma unroll
                    for (int k = 0; k < 9; k++) w2[k] = pk(wr[ci * 9 + k], wr[ci * 9 + k]);
#pragma unroll
                    for (int j = 0; j < 8; j++) {
                        int X = 2 * (pg * 8 + j);
                        const float* base = &xs[(ci * 34 + Y) * 34 + X];
                        ull q[4][3];
#pragma unroll
                        for (int r = 0; r < 4; r++) {
                            float2 ra = *(const float2*)(base + r * 34);
                            float2 rb = *(const float2*)(base + r * 34 + 2);
                            q[r][0] = pk(ra.x, ra.y);
                            q[r][1] = pk(ra.y, rb.x);
                            q[r][2] = pk(rb.x, rb.y);
                        }
#pragma unroll
                        for (int dy = 0; dy < 3; dy++)
#pragma unroll
                            for (int dxj = 0; dxj < 3; dxj++) {
                                acc0[j] = ffma2(q[dy][dxj],     w2[dy * 3 + dxj], acc0[j]);
                                acc1[j] = ffma2(q[dy + 1][dxj], w2[dy * 3 + dxj], acc1[j]);
                            }
                    }
                }
#pragma unroll
                for (int j = 0; j < 8; j++) {
                    int px = pg * 8 + j;
                    float a00, a01, a10, a11;
                    upk(acc0[j], a00, a01);
                    upk(acc1[j], a10, a11);
                    float v = fmaxf(fmaxf(fmaxf(a00, a01), fmaxf(a10, a11)), 0.f);
                    __half h = __float2half_rn(v);
                    int pix = (py + 1) * 18 + (px + 1);
                    BHp[pix * ROWP + co] = h;
                    BLp[pix * ROWP + co] = __float2half_rn(v - __half2float(h));
                }
            }
        }
    }
    __syncthreads();   // conv1 output complete; xs dead

    // ---- conv2 ----
    const __half* wsrch = g_w2h + (size_t)e * 9 * C2 * C1;
    const __half* wsrcl = g_w2l + (size_t)e * 9 * C2 * C1;

    int arow = tid >> 2, aseg = tid & 3;
    auto stageA = [&](int tap, int buf) {
        const uint4* sh = (const uint4*)&wsrch[(size_t)(tap * C2 + arow) * C1 + aseg * 16];
        const uint4* sl = (const uint4*)&wsrcl[(size_t)(tap * C2 + arow) * C1 + aseg * 16];
        uint4* dh = (uint4*)(smem + OFF_A2 + buf * A_BUF_SZ + (arow * ROWP + aseg * 16) * 2);
        uint4* dl = (uint4*)(smem + OFF_A2 + buf * A_BUF_SZ + C2 * ROWP * 2
                             + (arow * ROWP + aseg * 16) * 2);
        dh[0] = sh[0]; dh[1] = sh[1];
        dl[0] = sl[0]; dl[1] = sl[1];
    };

    stageA(0, 0);
    __syncthreads();

    int warp_m  = wid >> 2;
    int warp_n  = wid & 3;
    int co_base = warp_m * 32;

    float acc[2][8][4];
#pragma unroll
    for (int mt = 0; mt < 2; mt++)
#pragma unroll
        for (int nt = 0; nt < 8; nt++)
#pragma unroll
            for (int j = 0; j < 4; j++) acc[mt][nt][j] = 0.f;

    uint32_t a_off = (uint32_t)((lane & 15) * ROWP + (lane >> 4) * 8) * 2;
    uint32_t b_off = (uint32_t)(((lane & 7) + ((lane >> 4) << 3)) * ROWP * 2)
                   + (uint32_t)(((lane >> 3) & 1) * 16);

    for (int tap = 0; tap < 9; tap++) {
        if (tap + 1 < 9) stageA(tap + 1, (tap + 1) & 1);
        int dy = tap / 3, dx = tap % 3;
        uint32_t abase_h = sb + OFF_A2 + (tap & 1) * A_BUF_SZ;
        uint32_t abase_l = abase_h + C2 * ROWP * 2;

#pragma unroll
        for (int ks = 0; ks < 4; ks++) {
            uint32_t kso = (uint32_t)(ks * 32);
            uint32_t a_h[2][4], a_l[2][4];
#pragma unroll
            for (int mt = 0; mt < 2; mt++) {
                uint32_t ra = (uint32_t)((co_base + mt * 16) * ROWP * 2) + a_off + kso;
                ldsm_x4(a_h[mt][0], a_h[mt][1], a_h[mt][2], a_h[mt][3], abase_h + ra);
                ldsm_x4(a_l[mt][0], a_l[mt][1], a_l[mt][2], a_l[mt][3], abase_l + ra);
            }
#pragma unroll
            for (int ntp = 0; ntp < 4; ntp++) {
                int y  = warp_n * 4 + ntp;
                uint32_t rrow = (uint32_t)((y + dy) * 18 + dx);
                uint32_t rb   = rrow * (ROWP * 2) + b_off + kso;
                uint32_t bh0, bh1, bh2, bh3, bl0, bl1, bl2, bl3;
                ldsm_x4(bh0, bh1, bh2, bh3, sb + OFF_BH2 + rb);
                ldsm_x4(bl0, bl1, bl2, bl3, sb + OFF_BL2 + rb);
                int nt0 = 2 * ntp, nt1 = 2 * ntp + 1;
#pragma unroll
                for (int mt = 0; mt < 2; mt++) {
                    mma16816(acc[mt][nt0], a_h[mt], bh0, bh1);
                    mma16816(acc[mt][nt0], a_h[mt], bl0, bl1);
                    mma16816(acc[mt][nt0], a_l[mt], bh0, bh1);
                    mma16816(acc[mt][nt1], a_h[mt], bh2, bh3);
                    mma16816(acc[mt][nt1], a_h[mt], bl2, bl3);
                    mma16816(acc[mt][nt1], a_l[mt], bh2, bh3);
                }
            }
        }
        __syncthreads();
    }

    int r  = lane >> 2;
    int c2 = lane & 3;
    float* dstb = g_buf2 + (size_t)b * FCIN;
#pragma unroll
    for (int mt = 0; mt < 2; mt++) {
#pragma unroll
        for (int rg = 0; rg < 2; rg++) {
            int co = co_base + mt * 16 + r + rg * 8;
            float bias = c2b[e * C2 + co];
#pragma unroll
            for (int q = 0; q < 4; q++) {
                int ntp = (q & 1) + (q >> 1) * 4;   // 0,1,4,5
                float m = fmaxf(
                    fmaxf(acc[mt][ntp][rg * 2],     acc[mt][ntp][rg * 2 + 1]),
                    fmaxf(acc[mt][ntp + 2][rg * 2], acc[mt][ntp + 2][rg * 2 + 1]));
                int py = warp_n * 2 + (ntp >> 2);
                int px = (ntp & 1) * 4 + c2;
                dstb[co * 64 + py * 8 + px] = fmaxf(m + bias, 0.f);
            }
        }
    }
}

// ---------------- expert FC: gathered mini-GEMM, f32x2 over k ----------------
#define FC_SPB 8
__global__ void __launch_bounds__(256) fc_kernel(
    const float* __restrict__ fw, const float* __restrict__ fb,
    float* __restrict__ out)
{
    int e     = blockIdx.x >> 7;
    int chunk = blockIdx.x & 127;
    int n  = g_count[e];
    int s0 = chunk * FC_SPB;
    if (s0 >= n) return;
    int m = n - s0; if (m > FC_SPB) m = FC_SPB;

    __shared__ float As[FC_SPB][128];
    __shared__ int   sidx[FC_SPB];

    int tid = threadIdx.x;
    if (tid < FC_SPB) {
        sidx[tid] = g_list[e * B + ((tid < m) ? (s0 + tid) : s0)];
    }
    __syncthreads();

    int sg = tid / 50;
    int cg = tid % 50;
    bool act = (tid < 200);

    ull c00 = 0, c01 = 0, c10 = 0, c11 = 0;
    const float* w0 = fw + ((size_t)e * NC + cg * 2) * FCIN;
    const float* w1 = w0 + FCIN;

    int fr  = tid >> 5;
    int fk4 = (tid & 31) * 4;

    for (int k0 = 0; k0 < FCIN; k0 += 128) {
        __syncthreads();
        *(float4*)&As[fr][fk4] =
            *(const float4*)&g_buf2[(size_t)sidx[fr] * FCIN + k0 + fk4];
        __syncthreads();
        if (act) {
            const float* a0 = As[sg * 2];
            const float* a1 = As[sg * 2 + 1];
#pragma unroll 16
            for (int kk = 0; kk < 128; kk += 2) {
                ull wa = *(const ull*)(w0 + k0 + kk);
                ull wb = *(const ull*)(w1 + k0 + kk);
                ull v0 = *(const ull*)(a0 + kk);
                ull v1 = *(const ull*)(a1 + kk);
                c00 = ffma2(v0, wa, c00);
                c01 = ffma2(v0, wb, c01);
                c10 = ffma2(v1, wa, c10);
                c11 = ffma2(v1, wb, c11);
            }
        }
    }

    if (act) {
        float lo, hi;
        float a[2][2];
        upk(c00, lo, hi); a[0][0] = lo + hi;
        upk(c01, lo, hi); a[0][1] = lo + hi;
        upk(c10, lo, hi); a[1][0] = lo + hi;
        upk(c11, lo, hi); a[1][1] = lo + hi;
#pragma unroll
        for (int si = 0; si < 2; si++) {
            int rr = sg * 2 + si;
            if (rr < m) {
                int s = sidx[rr];
                float scale = g_bw[s];
#pragma unroll
                for (int cj = 0; cj < 2; cj++) {
                    int c = cg * 2 + cj;
                    out[(size_t)s * NC + c] = (a[si][cj] + fb[e * NC + c]) * scale;
                }
            }
        }
    }
}

// ---------------- launch ----------------
extern "C" void kernel_launch(void* const* d_in, const int* in_sizes, int n_in,
                              void* d_out, int out_size)
{
    const float* x       = (const float*)d_in[0];
    const float* gate_cw = (const float*)d_in[1];
    const float* gate_cb = (const float*)d_in[2];
    const float* gate_fw = (const float*)d_in[3];
    const float* gate_fb = (const float*)d_in[4];
    const float* e_c1w   = (const float*)d_in[5];
    const float* e_c1b   = (const float*)d_in[6];
    const float* e_c2w   = (const float*)d_in[7];
    const float* e_c2b   = (const float*)d_in[8];
    const float* e_fw    = (const float*)d_in[9];
    const float* e_fb    = (const float*)d_in[10];
    float* out = (float*)d_out;

    cudaFuncSetAttribute(conv12_fused_kernel,
                         cudaFuncAttributeMaxDynamicSharedMemorySize, C2_SMEM);

    prep_w2_kernel<<<(E * 9 * C2 * C1 + 255) / 256, 256>>>(e_c2w);
    gate_conv_kernel<<<B, 256>>>(x, gate_cw, gate_cb);
    router_kernel<<<B / 256, 256>>>(gate_fw, gate_fb, out + OUT_PROBS_OFF);
    aux_kernel<<<1, 256>>>(out + OUT_PROBS_OFF, out + OUT_AUX_OFF);
    conv12_fused_kernel<<<B, 512, C2_SMEM>>>(x, e_c1w, e_c1b, e_c2b);
    fc_kernel<<<E * 128, 256>>>(e_fw, e_fb, out);
}